// round 12
// baseline (speedup 1.0000x reference)
#include <cuda_runtime.h>
#include <cuda_fp16.h>
#include <math.h>
#include <stdint.h>

#define SQc  8192
#define SKc  8192
#define DHc  128
#define BMc  64
#define BNc  64
#define KSPLIT 2
#define NTILES (SKc / KSPLIT / BNc)   // 64
#define NT   128

#define LOG2E 1.4426950408889634f

// ---------------- global scratch (static; no allocation) ----------------
__device__ __align__(256) __half g_Qh[SQc * DHc];
__device__ __align__(256) __half g_Ql[SQc * DHc];
__device__ __align__(256) __half g_Kh[SKc * DHc];
__device__ __align__(256) __half g_Kl[SKc * DHc];
__device__ __align__(256) __half g_Vt[DHc * SKc];     // V transposed: [d][key]
__device__ __align__(256) float g_Opart[KSPLIT][SQc * DHc];
__device__ __align__(256) float g_lpart[KSPLIT][SQc];
__device__ __align__(256) float g_mpart[KSPLIT][SQc]; // row max (natural domain)

// ---------------- helpers ----------------
__device__ __forceinline__ uint32_t sw128(uint32_t o) { return o ^ ((o >> 3) & 0x70); }

__device__ __forceinline__ uint32_t smem_u32(const void* p) {
    uint32_t a;
    asm("{ .reg .u64 t; cvta.to.shared.u64 t, %1; cvt.u32.u64 %0, t; }" : "=r"(a) : "l"(p));
    return a;
}

__device__ __forceinline__ void cp16(uint32_t dst, const void* src) {
    asm volatile("cp.async.cg.shared.global [%0], [%1], 16;" :: "r"(dst), "l"(src));
}
__device__ __forceinline__ void cp_commit() { asm volatile("cp.async.commit_group;" ::: "memory"); }

__device__ __forceinline__ void ldsm4(uint32_t* r, uint32_t addr) {
    asm volatile("ldmatrix.sync.aligned.m8n8.x4.shared.b16 {%0,%1,%2,%3}, [%4];"
        : "=r"(r[0]), "=r"(r[1]), "=r"(r[2]), "=r"(r[3]) : "r"(addr));
}

__device__ __forceinline__ void mma16816(float* d, const uint32_t* a, uint32_t b0, uint32_t b1) {
    asm volatile(
        "mma.sync.aligned.m16n8k16.row.col.f32.f16.f16.f32 "
        "{%0,%1,%2,%3}, {%4,%5,%6,%7}, {%8,%9}, {%0,%1,%2,%3};"
        : "+f"(d[0]), "+f"(d[1]), "+f"(d[2]), "+f"(d[3])
        : "r"(a[0]), "r"(a[1]), "r"(a[2]), "r"(a[3]), "r"(b0), "r"(b1));
}

__device__ __forceinline__ float ex2f(float x) {
    float r;
    asm("ex2.approx.f32 %0, %1;" : "=f"(r) : "f"(x));
    return r;
}

__device__ __forceinline__ uint32_t packh2(float lo, float hi) {
    uint32_t u;
    asm("cvt.rn.f16x2.f32 %0, %1, %2;" : "=r"(u) : "f"(hi), "f"(lo));
    return u;
}

// packed fp16x2 exp2: input two f32, output two fp16 = 2^input
__device__ __forceinline__ uint32_t ex2h2(float z0, float z1) {
    uint32_t zp, pp;
    asm("cvt.rn.f16x2.f32 %0, %1, %2;" : "=r"(zp) : "f"(z1), "f"(z0));
    asm("ex2.approx.f16x2 %0, %1;" : "=r"(pp) : "r"(zp));
    return pp;
}

// ---------------- preprocessing ----------------
__global__ void convert_qk(const float4* __restrict__ Q, const float4* __restrict__ K) {
    int i = blockIdx.x * 256 + threadIdx.x;
    float4 q = Q[i];
    uint32_t h01 = packh2(q.x, q.y);
    uint32_t h23 = packh2(q.z, q.w);
    float2 f01 = __half22float2(*(__half2*)&h01);
    float2 f23 = __half22float2(*(__half2*)&h23);
    ((uint2*)g_Qh)[i] = make_uint2(h01, h23);
    ((uint2*)g_Ql)[i] = make_uint2(packh2(q.x - f01.x, q.y - f01.y),
                                   packh2(q.z - f23.x, q.w - f23.y));
    float4 k = K[i];
    h01 = packh2(k.x, k.y);
    h23 = packh2(k.z, k.w);
    f01 = __half22float2(*(__half2*)&h01);
    f23 = __half22float2(*(__half2*)&h23);
    ((uint2*)g_Kh)[i] = make_uint2(h01, h23);
    ((uint2*)g_Kl)[i] = make_uint2(packh2(k.x - f01.x, k.y - f01.y),
                                   packh2(k.z - f23.x, k.w - f23.y));
}

__global__ void convert_vt(const float* __restrict__ V) {
    __shared__ float t[32][33];
    int s0 = blockIdx.x * 32, d0 = blockIdx.y * 32;
    int tx = threadIdx.x, ty = threadIdx.y;   // 32 x 8
    #pragma unroll
    for (int i = 0; i < 4; i++)
        t[ty * 4 + i][tx] = V[(size_t)(s0 + ty * 4 + i) * DHc + d0 + tx];
    __syncthreads();
    int tid = ty * 32 + tx;
    int dl = tid >> 3;
    int sl = (tid & 7) * 4;
    __half2 h0 = __floats2half2_rn(t[sl][dl],     t[sl + 1][dl]);
    __half2 h1 = __floats2half2_rn(t[sl + 2][dl], t[sl + 3][dl]);
    uint2 u; u.x = *(uint32_t*)&h0; u.y = *(uint32_t*)&h1;
    *(uint2*)&g_Vt[(size_t)(d0 + dl) * SKc + s0 + sl] = u;
}

__global__ void combine_out(float4* __restrict__ O) {
    int i = blockIdx.x * 256 + threadIdx.x;     // 1 float4 per thread
    int row = i >> 5;
    float4 a = ((const float4*)g_Opart[0])[i];
    float4 b = ((const float4*)g_Opart[1])[i];
    float m0 = g_mpart[0][row], m1 = g_mpart[1][row];
    float M = fmaxf(m0, m1);
    float w0 = ex2f((m0 - M) * LOG2E), w1 = ex2f((m1 - M) * LOG2E);
    float inv = 1.0f / (g_lpart[0][row] * w0 + g_lpart[1][row] * w1);
    w0 *= inv; w1 *= inv;
    float4 r;
    r.x = a.x * w0 + b.x * w1;
    r.y = a.y * w0 + b.y * w1;
    r.z = a.z * w0 + b.z * w1;
    r.w = a.w * w0 + b.w * w1;
    O[i] = r;
}

// ---------------- main kernel ----------------
// stage layout (48KB): Kh c0 @0, Kh c1 @8192, Kl c0 @16384, Kl c1 @24576, Vt @32768 (16K)
// 2 stages x 48KB = 96KB per CTA -> 2 CTAs / SM.
#define STG        49152
#define SMEM_TOTAL (2 * STG)

__device__ __forceinline__ void load_tile(uint32_t SB, int kb, int tid) {
    #pragma unroll
    for (int it = 0; it < 24; it++) {
        int u = it * NT + tid;
        if (u < 2048) {                 // K: split(hi/lo) x chunk x 64 rows x 8 units
            int sp = u >> 10;
            int i  = u & 1023;
            int ch = i >> 9;
            int r  = (i >> 3) & 63;
            int cb = i & 7;
            uint32_t dst = SB + (uint32_t)sp * 16384u + (uint32_t)ch * 8192u
                         + sw128((uint32_t)(r * 128 + cb * 16));
            const __half* src = (sp ? g_Kl : g_Kh) + ((size_t)(kb + r) * DHc + ch * 64 + cb * 8);
            cp16(dst, src);
        } else {                        // Vt: 128 d-rows x 8 units
            int v  = u - 2048;
            int r  = v >> 3;
            int cb = v & 7;
            uint32_t dst = SB + 32768u + sw128((uint32_t)(r * 128 + cb * 16));
            const __half* src = g_Vt + ((size_t)r * SKc + kb + cb * 8);
            cp16(dst, src);
        }
    }
}

__global__ void __launch_bounds__(NT) attn_hmma() {
    extern __shared__ char smem[];
    const uint32_t sb  = smem_u32(smem);
    const int tid   = threadIdx.x;
    const int w     = tid >> 5;
    const int lane  = tid & 31;
    const int wbase = w * 16;           // 4 warps x 16 rows = 64 rows
    const int qb    = blockIdx.x * BMc;
    const int ky    = blockIdx.y;
    const int kb0   = ky * (SKc / KSPLIT);

    // ---- stage Q: Qh -> stage0 region, Ql -> stage1 region (transient) ----
    #pragma unroll
    for (int it = 0; it < 16; it++) {
        int u  = it * NT + tid;         // 0..2047
        int sp = u >> 10;               // 0: hi, 1: lo
        int i  = u & 1023;
        int ch = i >> 9;
        int r  = (i >> 3) & 63;
        int cb = i & 7;
        uint32_t base = sb + (uint32_t)sp * STG;
        uint32_t dst  = base + (uint32_t)ch * 8192u + sw128((uint32_t)(r * 128 + cb * 16));
        const __half* src = (sp ? g_Ql : g_Qh) + ((size_t)(qb + r) * DHc + ch * 64 + cb * 8);
        cp16(dst, src);
    }
    cp_commit();
    asm volatile("cp.async.wait_group 0;" ::: "memory");
    __syncthreads();

    // ---- Qh and Ql A-fragments -> registers (once) ----
    const int krow_b = (lane & 7) * 128 + ((lane >> 3) & 3) * 16;
    const int arow   = wbase + ((lane >> 3) & 1) * 8 + (lane & 7);
    const int adb    = (lane >> 4) * 16;
    const int vrow_b = (((lane >> 4) & 1) * 8 + (lane & 7)) * 128 + ((lane >> 3) & 1) * 16;

    uint32_t qh[8][4], ql[8][4];
    #pragma unroll
    for (int ks = 0; ks < 8; ks++) {
        int ch  = ks >> 2;
        uint32_t off = (uint32_t)ch * 8192u
                     + sw128((uint32_t)(arow * 128 + (ks & 3) * 32 + adb));
        ldsm4(qh[ks], sb + off);
        ldsm4(ql[ks], sb + STG + off);
    }
    __syncthreads();

    // prologue: tile 0 in flight
    load_tile(sb + 0 * STG, kb0 + 0 * BNc, tid); cp_commit();

    float o[16][4];
    #pragma unroll
    for (int n = 0; n < 16; n++)
        #pragma unroll
        for (int j = 0; j < 4; j++) o[n][j] = 0.0f;
    float lacc[4] = {0.0f, 0.0f, 0.0f, 0.0f};
    float m0 = -INFINITY, m1 = -INFINITY;
    const uint32_t ONESH2 = 0x3C003C00u;        // fp16 {1.0, 1.0}

    for (int t = 0; t < NTILES; t++) {
        const uint32_t SB = sb + (uint32_t)(t & 1) * STG;

        asm volatile("cp.async.wait_group 0;" ::: "memory");
        __syncthreads();    // tile t resident; everyone done reading stage (t+1)&1

        if (t + 1 < NTILES) {
            load_tile(sb + (uint32_t)((t + 1) & 1) * STG, kb0 + (t + 1) * BNc, tid);
            cp_commit();
        }

        // ---- S = (Qh+Ql)(Kh+Kl)^T, all f32 accum ----
        float s[8][4];
        #pragma unroll
        for (int n = 0; n < 8; n++)
            #pragma unroll
            for (int j = 0; j < 4; j++) s[n][j] = 0.0f;

        #pragma unroll
        for (int ch = 0; ch < 2; ch++) {
            #pragma unroll
            for (int ks2 = 0; ks2 < 2; ks2++) {
                const int ksA = ch * 4 + ks2 * 2;
                uint32_t bh[8][4];
                #pragma unroll
                for (int n = 0; n < 8; n++)
                    ldsm4(bh[n], SB + (uint32_t)ch * 8192u
                                 + sw128((uint32_t)(n * 1024 + ks2 * 64 + krow_b)));
                #pragma unroll
                for (int n = 0; n < 8; n++) {
                    mma16816(s[n], qh[ksA],     bh[n][0], bh[n][1]);
                    mma16816(s[n], qh[ksA + 1], bh[n][2], bh[n][3]);
                    mma16816(s[n], ql[ksA],     bh[n][0], bh[n][1]);
                    mma16816(s[n], ql[ksA + 1], bh[n][2], bh[n][3]);
                }
                uint32_t bl[8][4];
                #pragma unroll
                for (int n = 0; n < 8; n++)
                    ldsm4(bl[n], SB + 16384u + (uint32_t)ch * 8192u
                                 + sw128((uint32_t)(n * 1024 + ks2 * 64 + krow_b)));
                #pragma unroll
                for (int n = 0; n < 8; n++) {
                    mma16816(s[n], qh[ksA],     bl[n][0], bl[n][1]);
                    mma16816(s[n], qh[ksA + 1], bl[n][2], bl[n][3]);
                }
            }
        }

        // ---- online softmax (row max; packed fp16 exp) ----
        float t0 = s[0][0], t1 = s[0][2];
        #pragma unroll
        for (int n = 0; n < 8; n++) {
            t0 = fmaxf(t0, fmaxf(s[n][0], s[n][1]));
            t1 = fmaxf(t1, fmaxf(s[n][2], s[n][3]));
        }
        t0 = fmaxf(t0, __shfl_xor_sync(0xffffffffu, t0, 1));
        t0 = fmaxf(t0, __shfl_xor_sync(0xffffffffu, t0, 2));
        t1 = fmaxf(t1, __shfl_xor_sync(0xffffffffu, t1, 1));
        t1 = fmaxf(t1, __shfl_xor_sync(0xffffffffu, t1, 2));

        float mn0 = fmaxf(m0, t0), mn1 = fmaxf(m1, t1);
        float a0 = ex2f((m0 - mn0) * LOG2E), a1 = ex2f((m1 - mn1) * LOG2E);
        m0 = mn0; m1 = mn1;

        if (!__all_sync(0xffffffffu, (a0 == 1.0f) & (a1 == 1.0f))) {
            #pragma unroll
            for (int n = 0; n < 16; n++) {
                o[n][0] *= a0; o[n][1] *= a0;
                o[n][2] *= a1; o[n][3] *= a1;
            }
            lacc[0] *= a0; lacc[1] *= a0;
            lacc[2] *= a1; lacc[3] *= a1;
        }

        const float nm0 = -mn0 * LOG2E, nm1 = -mn1 * LOG2E;
        uint32_t ph[8][2];
        #pragma unroll
        for (int n = 0; n < 8; n++) {
            ph[n][0] = ex2h2(fmaf(s[n][0], LOG2E, nm0), fmaf(s[n][1], LOG2E, nm0));
            ph[n][1] = ex2h2(fmaf(s[n][2], LOG2E, nm1), fmaf(s[n][3], LOG2E, nm1));
        }

        // ---- O += P V ; l += P * ones (tensor-core row sum) ----
        #pragma unroll
        for (int ks = 0; ks < 4; ks++) {
            uint32_t A[4] = { ph[2 * ks][0], ph[2 * ks][1],
                              ph[2 * ks + 1][0], ph[2 * ks + 1][1] };
            mma16816(lacc, A, ONESH2, ONESH2);
            uint32_t bv[8][4];
            #pragma unroll
            for (int dp = 0; dp < 8; dp++)
                ldsm4(bv[dp], SB + 32768u
                              + sw128((uint32_t)(dp * 2048 + ks * 32 + vrow_b)));
            #pragma unroll
            for (int dp = 0; dp < 8; dp++) {
                mma16816(o[2 * dp],     A, bv[dp][0], bv[dp][1]);
                mma16816(o[2 * dp + 1], A, bv[dp][2], bv[dp][3]);
            }
        }
    }

    // ---- epilogue ----
    int r0 = qb + wbase + (lane >> 2);
    int r1 = r0 + 8;
    int c2 = (lane & 3) * 2;
    float* op = g_Opart[ky];
    #pragma unroll
    for (int n = 0; n < 16; n++) {
        *(float2*)&op[(size_t)r0 * DHc + n * 8 + c2] = make_float2(o[n][0], o[n][1]);
        *(float2*)&op[(size_t)r1 * DHc + n * 8 + c2] = make_float2(o[n][2], o[n][3]);
    }
    if ((lane & 3) == 0) {
        g_lpart[ky][r0] = lacc[0];  g_lpart[ky][r1] = lacc[2];
        g_mpart[ky][r0] = m0;       g_mpart[ky][r1] = m1;
    }
}

// ---------------- launcher ----------------
extern "C" void kernel_launch(void* const* d_in, const int* in_sizes, int n_in,
                              void* d_out, int out_size)
{
    const float* Q = (const float*)d_in[0];
    const float* K = (const float*)d_in[1];
    const float* V = (const float*)d_in[2];
    float* O = (float*)d_out;

    cudaFuncSetAttribute(attn_hmma, cudaFuncAttributeMaxDynamicSharedMemorySize, SMEM_TOTAL);

    convert_qk<<<SQc * DHc / 4 / 256, 256>>>((const float4*)Q, (const float4*)K);
    convert_vt<<<dim3(SKc / 32, DHc / 32), dim3(32, 8)>>>(V);
    attn_hmma<<<dim3(SQc / BMc, KSPLIT), NT, SMEM_TOTAL>>>();
    combine_out<<<SQc * DHc / 4 / 256, 256>>>((float4*)O);
}

// round 13
// speedup vs baseline: 1.1225x; 1.1225x over previous
#include <cuda_runtime.h>
#include <cuda_fp16.h>
#include <math.h>
#include <stdint.h>

#define SQc  8192
#define SKc  8192
#define DHc  128
#define BMc  128
#define BNc  64
#define NQT  (SQc / BMc)          // 64 q-tiles
#define NKT  (SKc / BNc)          // 128 k-tiles
#define TTOT (NQT * NKT)          // 8192 global tile-pairs
#define NCTA 148
#define NT   256

#define LOG2E 1.4426950408889634f

// ---------------- global scratch (static; no allocation) ----------------
__device__ __align__(256) __half g_Qh[SQc * DHc];
__device__ __align__(256) __half g_Ql[SQc * DHc];
__device__ __align__(256) __half g_Kh[SKc * DHc];
__device__ __align__(256) __half g_Kl[SKc * DHc];
__device__ __align__(256) __half g_Vt[DHc * SKc];     // V transposed: [d][key]
// per-CTA partials: each CTA covers <= 2 q-tiles (range <= 56 < 128)
__device__ __align__(256) float g_pO[NCTA][2][BMc * DHc];
__device__ __align__(256) float g_pl[NCTA][2][BMc];
__device__ __align__(256) float g_pm[NCTA][2][BMc];

__device__ __forceinline__ int cta_start(int c) {
    return (int)(((long long)c * TTOT) / NCTA);
}

// ---------------- helpers ----------------
__device__ __forceinline__ uint32_t sw128(uint32_t o) { return o ^ ((o >> 3) & 0x70); }

__device__ __forceinline__ uint32_t smem_u32(const void* p) {
    uint32_t a;
    asm("{ .reg .u64 t; cvta.to.shared.u64 t, %1; cvt.u32.u64 %0, t; }" : "=r"(a) : "l"(p));
    return a;
}

__device__ __forceinline__ void cp16(uint32_t dst, const void* src) {
    asm volatile("cp.async.cg.shared.global [%0], [%1], 16;" :: "r"(dst), "l"(src));
}
__device__ __forceinline__ void cp_commit() { asm volatile("cp.async.commit_group;" ::: "memory"); }

__device__ __forceinline__ void ldsm4(uint32_t* r, uint32_t addr) {
    asm volatile("ldmatrix.sync.aligned.m8n8.x4.shared.b16 {%0,%1,%2,%3}, [%4];"
        : "=r"(r[0]), "=r"(r[1]), "=r"(r[2]), "=r"(r[3]) : "r"(addr));
}

__device__ __forceinline__ void mma16816(float* d, const uint32_t* a, uint32_t b0, uint32_t b1) {
    asm volatile(
        "mma.sync.aligned.m16n8k16.row.col.f32.f16.f16.f32 "
        "{%0,%1,%2,%3}, {%4,%5,%6,%7}, {%8,%9}, {%0,%1,%2,%3};"
        : "+f"(d[0]), "+f"(d[1]), "+f"(d[2]), "+f"(d[3])
        : "r"(a[0]), "r"(a[1]), "r"(a[2]), "r"(a[3]), "r"(b0), "r"(b1));
}

__device__ __forceinline__ float ex2f(float x) {
    float r;
    asm("ex2.approx.f32 %0, %1;" : "=f"(r) : "f"(x));
    return r;
}

__device__ __forceinline__ uint32_t packh2(float lo, float hi) {
    uint32_t u;
    asm("cvt.rn.f16x2.f32 %0, %1, %2;" : "=r"(u) : "f"(hi), "f"(lo));
    return u;
}

__device__ __forceinline__ uint32_t ex2h2(float z0, float z1) {
    uint32_t zp, pp;
    asm("cvt.rn.f16x2.f32 %0, %1, %2;" : "=r"(zp) : "f"(z1), "f"(z0));
    asm("ex2.approx.f16x2 %0, %1;" : "=r"(pp) : "r"(zp));
    return pp;
}

// ---------------- preprocessing ----------------
__global__ void convert_qk(const float4* __restrict__ Q, const float4* __restrict__ K) {
    int i = blockIdx.x * 256 + threadIdx.x;
    float4 q = Q[i];
    uint32_t h01 = packh2(q.x, q.y);
    uint32_t h23 = packh2(q.z, q.w);
    float2 f01 = __half22float2(*(__half2*)&h01);
    float2 f23 = __half22float2(*(__half2*)&h23);
    ((uint2*)g_Qh)[i] = make_uint2(h01, h23);
    ((uint2*)g_Ql)[i] = make_uint2(packh2(q.x - f01.x, q.y - f01.y),
                                   packh2(q.z - f23.x, q.w - f23.y));
    float4 k = K[i];
    h01 = packh2(k.x, k.y);
    h23 = packh2(k.z, k.w);
    f01 = __half22float2(*(__half2*)&h01);
    f23 = __half22float2(*(__half2*)&h23);
    ((uint2*)g_Kh)[i] = make_uint2(h01, h23);
    ((uint2*)g_Kl)[i] = make_uint2(packh2(k.x - f01.x, k.y - f01.y),
                                   packh2(k.z - f23.x, k.w - f23.y));
}

__global__ void convert_vt(const float* __restrict__ V) {
    __shared__ float t[32][33];
    int s0 = blockIdx.x * 32, d0 = blockIdx.y * 32;
    int tx = threadIdx.x, ty = threadIdx.y;   // 32 x 8
    #pragma unroll
    for (int i = 0; i < 4; i++)
        t[ty * 4 + i][tx] = V[(size_t)(s0 + ty * 4 + i) * DHc + d0 + tx];
    __syncthreads();
    int tid = ty * 32 + tx;
    int dl = tid >> 3;
    int sl = (tid & 7) * 4;
    __half2 h0 = __floats2half2_rn(t[sl][dl],     t[sl + 1][dl]);
    __half2 h1 = __floats2half2_rn(t[sl + 2][dl], t[sl + 3][dl]);
    uint2 u; u.x = *(uint32_t*)&h0; u.y = *(uint32_t*)&h1;
    *(uint2*)&g_Vt[(size_t)(d0 + dl) * SKc + s0 + sl] = u;
}

// merge <=4 per-CTA partials per q-row
__global__ void combine_out(float4* __restrict__ O) {
    int idx = blockIdx.x * 256 + threadIdx.x;   // SQ * 32 float4
    int row = idx >> 5;
    int c4  = idx & 31;
    int qt  = row >> 7, qr = row & 127;
    int t0  = qt << 7, t1 = t0 + BMc;

    int c = (int)(((long long)t0 * NCTA) / TTOT);
    while (cta_start(c + 1) <= t0) c++;

    float pm_[4], pw_[4];
    int   pc_[4], ps_[4];
    int np = 0;
    float M = -INFINITY;
    for (; c < NCTA && cta_start(c) < t1 && np < 4; c++) {
        int slot = qt - (cta_start(c) >> 7);
        float m = g_pm[c][slot][qr];
        pm_[np] = m; pc_[np] = c; ps_[np] = slot; np++;
        M = fmaxf(M, m);
    }
    float L = 0.0f;
    for (int i = 0; i < np; i++) {
        float w = ex2f((pm_[i] - M) * LOG2E);
        pw_[i] = w;
        L += g_pl[pc_[i]][ps_[i]][qr] * w;
    }
    float inv = 1.0f / L;
    float4 r = make_float4(0.f, 0.f, 0.f, 0.f);
    for (int i = 0; i < np; i++) {
        float4 a = *(const float4*)&g_pO[pc_[i]][ps_[i]][qr * DHc + c4 * 4];
        float w = pw_[i] * inv;
        r.x += a.x * w; r.y += a.y * w; r.z += a.z * w; r.w += a.w * w;
    }
    O[(size_t)row * 32 + c4] = r;
}

// ---------------- main kernel ----------------
// stage (48KB): Kh c0 @0, Kh c1 @8192, Kl c0 @16384, Kl c1 @24576, Vt @32768 (16K)
#define STG        49152
#define QLB_OFF    (3 * STG)
#define SMEM_TOTAL (3 * STG + 32768)

__device__ __forceinline__ void load_tile(uint32_t SB, int kb, int tid) {
    #pragma unroll
    for (int it = 0; it < 12; it++) {
        int u = it * NT + tid;
        if (u < 2048) {
            int sp = u >> 10;
            int i  = u & 1023;
            int ch = i >> 9;
            int r  = (i >> 3) & 63;
            int cb = i & 7;
            uint32_t dst = SB + (uint32_t)sp * 16384u + (uint32_t)ch * 8192u
                         + sw128((uint32_t)(r * 128 + cb * 16));
            const __half* src = (sp ? g_Kl : g_Kh) + ((size_t)(kb + r) * DHc + ch * 64 + cb * 8);
            cp16(dst, src);
        } else {
            int v  = u - 2048;
            int r  = v >> 3;
            int cb = v & 7;
            uint32_t dst = SB + 32768u + sw128((uint32_t)(r * 128 + cb * 16));
            const __half* src = g_Vt + ((size_t)r * SKc + kb + cb * 8);
            cp16(dst, src);
        }
    }
}

__global__ void __launch_bounds__(NT, 1) attn_hmma() {
    extern __shared__ char smem[];
    const uint32_t sb  = smem_u32(smem);
    const uint32_t QLB = sb + QLB_OFF;
    const int tid   = threadIdx.x;
    const int w     = tid >> 5;
    const int lane  = tid & 31;
    const int wbase = w * 16;
    const int cidx  = blockIdx.x;
    const int gs    = cta_start(cidx);
    const int ge    = cta_start(cidx + 1);

    const int krow_b = (lane & 7) * 128 + ((lane >> 3) & 3) * 16;
    const int arow   = wbase + ((lane >> 3) & 1) * 8 + (lane & 7);
    const int adb    = (lane >> 4) * 16;
    const int vrow_b = (((lane >> 4) & 1) * 8 + (lane & 7)) * 128 + ((lane >> 3) & 1) * 16;
    const uint32_t ONESH2 = 0x3C003C00u;

    // prologue prefetch of first two K/V tiles
    load_tile(sb + (uint32_t)(gs % 3) * STG, (gs & (NKT - 1)) << 6, tid); cp_commit();
    load_tile(sb + (uint32_t)((gs + 1) % 3) * STG, ((gs + 1) & (NKT - 1)) << 6, tid); cp_commit();

    uint32_t qh[8][4];
    float o[16][4];
    float lacc[4];
    float m0 = -INFINITY, m1 = -INFINITY;
    int cur_qt = -1, slot = -1;

    for (int g = gs; g < ge; g++) {
        const int qt = g >> 7;   // NKT = 128

        if (qt != cur_qt) {
            // ---- flush previous q-tile partial ----
            if (slot >= 0) {
                int r0 = wbase + (lane >> 2), r1 = r0 + 8;
                int c2 = (lane & 3) * 2;
                float* op = g_pO[cidx][slot];
                #pragma unroll
                for (int n = 0; n < 16; n++) {
                    *(float2*)&op[r0 * DHc + n * 8 + c2] = make_float2(o[n][0], o[n][1]);
                    *(float2*)&op[r1 * DHc + n * 8 + c2] = make_float2(o[n][2], o[n][3]);
                }
                if ((lane & 3) == 0) {
                    g_pl[cidx][slot][r0] = lacc[0];  g_pl[cidx][slot][r1] = lacc[2];
                    g_pm[cidx][slot][r0] = m0;       g_pm[cidx][slot][r1] = m1;
                }
            }
            slot++;
            #pragma unroll
            for (int n = 0; n < 16; n++)
                #pragma unroll
                for (int j = 0; j < 4; j++) o[n][j] = 0.0f;
            lacc[0] = lacc[1] = lacc[2] = lacc[3] = 0.0f;
            m0 = -INFINITY; m1 = -INFINITY;

            // ---- load Q(qt): Qh -> free stage (g+2)%3, Ql -> QLB ----
            __syncthreads();   // all warps done with prior compute/stage reads
            const uint32_t QSTG = sb + (uint32_t)((g + 2) % 3) * STG;
            const int qrow0 = qt * BMc;
            #pragma unroll
            for (int it = 0; it < 16; it++) {
                int u  = it * NT + tid;         // 0..4095
                int sp = u >> 11;               // 0: Qh, 1: Ql
                int i  = u & 2047;
                int ch = i >> 10;
                int r  = (i >> 3) & 127;
                int cb = i & 7;
                uint32_t base = sp ? QLB : QSTG;
                uint32_t dst  = base + (uint32_t)ch * 16384u
                              + sw128((uint32_t)(r * 128 + cb * 16));
                const __half* src = (sp ? g_Ql : g_Qh)
                                  + ((size_t)(qrow0 + r) * DHc + ch * 64 + cb * 8);
                cp16(dst, src);
            }
            cp_commit();
            asm volatile("cp.async.wait_group 0;" ::: "memory");
            __syncthreads();
            #pragma unroll
            for (int ks = 0; ks < 8; ks++) {
                int ch = ks >> 2;
                ldsm4(qh[ks], QSTG + (uint32_t)ch * 16384u
                              + sw128((uint32_t)(arow * 128 + (ks & 3) * 32 + adb)));
            }
            cur_qt = qt;
            // iteration-top __syncthreads below orders these ldsm before
            // prefetch(g+2) overwrites QSTG
        }

        const uint32_t SB = sb + (uint32_t)(g % 3) * STG;

        if (g == ge - 1) asm volatile("cp.async.wait_group 0;" ::: "memory");
        else             asm volatile("cp.async.wait_group 1;" ::: "memory");
        __syncthreads();

        if (g + 2 < ge) {
            load_tile(sb + (uint32_t)((g + 2) % 3) * STG, ((g + 2) & (NKT - 1)) << 6, tid);
            cp_commit();
        }

        // ---- S = (Qh+Ql)(Kh+Kl)^T, all f32 accum ----
        float s[8][4];
        #pragma unroll
        for (int n = 0; n < 8; n++)
            #pragma unroll
            for (int j = 0; j < 4; j++) s[n][j] = 0.0f;

        #pragma unroll
        for (int ch = 0; ch < 2; ch++) {
            #pragma unroll
            for (int ks2 = 0; ks2 < 2; ks2++) {
                const int ksA = ch * 4 + ks2 * 2;
                uint32_t bh[8][4];
                #pragma unroll
                for (int n = 0; n < 8; n++)
                    ldsm4(bh[n], SB + (uint32_t)ch * 8192u
                                 + sw128((uint32_t)(n * 1024 + ks2 * 64 + krow_b)));
                uint32_t qlf[2][4];
                #pragma unroll
                for (int kd = 0; kd < 2; kd++) {
                    int ks  = ksA + kd;
                    int dby = (ks & 3) * 32 + adb;
                    ldsm4(qlf[kd], QLB + (uint32_t)ch * 16384u
                                   + sw128((uint32_t)(arow * 128 + dby)));
                }
                #pragma unroll
                for (int n = 0; n < 8; n++) {
                    mma16816(s[n], qh[ksA],     bh[n][0], bh[n][1]);
                    mma16816(s[n], qh[ksA + 1], bh[n][2], bh[n][3]);
                    mma16816(s[n], qlf[0],      bh[n][0], bh[n][1]);
                    mma16816(s[n], qlf[1],      bh[n][2], bh[n][3]);
                }
                uint32_t bl[8][4];
                #pragma unroll
                for (int n = 0; n < 8; n++)
                    ldsm4(bl[n], SB + 16384u + (uint32_t)ch * 8192u
                                 + sw128((uint32_t)(n * 1024 + ks2 * 64 + krow_b)));
                #pragma unroll
                for (int n = 0; n < 8; n++) {
                    mma16816(s[n], qh[ksA],     bl[n][0], bl[n][1]);
                    mma16816(s[n], qh[ksA + 1], bl[n][2], bl[n][3]);
                }
            }
        }

        // ---- online softmax ----
        float t0 = s[0][0], t1 = s[0][2];
        #pragma unroll
        for (int n = 0; n < 8; n++) {
            t0 = fmaxf(t0, fmaxf(s[n][0], s[n][1]));
            t1 = fmaxf(t1, fmaxf(s[n][2], s[n][3]));
        }
        t0 = fmaxf(t0, __shfl_xor_sync(0xffffffffu, t0, 1));
        t0 = fmaxf(t0, __shfl_xor_sync(0xffffffffu, t0, 2));
        t1 = fmaxf(t1, __shfl_xor_sync(0xffffffffu, t1, 1));
        t1 = fmaxf(t1, __shfl_xor_sync(0xffffffffu, t1, 2));

        float mn0 = fmaxf(m0, t0), mn1 = fmaxf(m1, t1);
        float a0 = ex2f((m0 - mn0) * LOG2E), a1 = ex2f((m1 - mn1) * LOG2E);
        m0 = mn0; m1 = mn1;

        if (!__all_sync(0xffffffffu, (a0 == 1.0f) & (a1 == 1.0f))) {
            #pragma unroll
            for (int n = 0; n < 16; n++) {
                o[n][0] *= a0; o[n][1] *= a0;
                o[n][2] *= a1; o[n][3] *= a1;
            }
            lacc[0] *= a0; lacc[1] *= a0;
            lacc[2] *= a1; lacc[3] *= a1;
        }

        const float nm0 = -mn0 * LOG2E, nm1 = -mn1 * LOG2E;
        uint32_t ph[8][2];
        #pragma unroll
        for (int n = 0; n < 8; n++) {
            ph[n][0] = ex2h2(fmaf(s[n][0], LOG2E, nm0), fmaf(s[n][1], LOG2E, nm0));
            ph[n][1] = ex2h2(fmaf(s[n][2], LOG2E, nm1), fmaf(s[n][3], LOG2E, nm1));
        }

        // ---- O += P V ; l += P * ones ----
        #pragma unroll
        for (int ks = 0; ks < 4; ks++) {
            uint32_t A[4] = { ph[2 * ks][0], ph[2 * ks][1],
                              ph[2 * ks + 1][0], ph[2 * ks + 1][1] };
            mma16816(lacc, A, ONESH2, ONESH2);
            uint32_t bv[8][4];
            #pragma unroll
            for (int dp = 0; dp < 8; dp++)
                ldsm4(bv[dp], SB + 32768u
                              + sw128((uint32_t)(dp * 2048 + ks * 32 + vrow_b)));
            #pragma unroll
            for (int dp = 0; dp < 8; dp++) {
                mma16816(o[2 * dp],     A, bv[dp][0], bv[dp][1]);
                mma16816(o[2 * dp + 1], A, bv[dp][2], bv[dp][3]);
            }
        }
    }

    // ---- final flush ----
    {
        int r0 = wbase + (lane >> 2), r1 = r0 + 8;
        int c2 = (lane & 3) * 2;
        float* op = g_pO[cidx][slot];
        #pragma unroll
        for (int n = 0; n < 16; n++) {
            *(float2*)&op[r0 * DHc + n * 8 + c2] = make_float2(o[n][0], o[n][1]);
            *(float2*)&op[r1 * DHc + n * 8 + c2] = make_float2(o[n][2], o[n][3]);
        }
        if ((lane & 3) == 0) {
            g_pl[cidx][slot][r0] = lacc[0];  g_pl[cidx][slot][r1] = lacc[2];
            g_pm[cidx][slot][r0] = m0;       g_pm[cidx][slot][r1] = m1;
        }
    }
}

// ---------------- launcher ----------------
extern "C" void kernel_launch(void* const* d_in, const int* in_sizes, int n_in,
                              void* d_out, int out_size)
{
    const float* Q = (const float*)d_in[0];
    const float* K = (const float*)d_in[1];
    const float* V = (const float*)d_in[2];
    float* O = (float*)d_out;

    cudaFuncSetAttribute(attn_hmma, cudaFuncAttributeMaxDynamicSharedMemorySize, SMEM_TOTAL);

    convert_qk<<<SQc * DHc / 4 / 256, 256>>>((const float4*)Q, (const float4*)K);
    convert_vt<<<dim3(SKc / 32, DHc / 32), dim3(32, 8)>>>(V);
    attn_hmma<<<NCTA, NT, SMEM_TOTAL>>>();
    combine_out<<<SQc * 32 / 256, 256>>>((float4*)O);
}

// round 16
// speedup vs baseline: 1.1362x; 1.0122x over previous
#include <cuda_runtime.h>
#include <cuda_fp16.h>
#include <math.h>
#include <stdint.h>

#define SQc  8192
#define SKc  8192
#define DHc  128
#define BMc  128
#define BNc  64
#define NQT  (SQc / BMc)          // 64 q-tiles
#define NKT  (SKc / BNc)          // 128 k-tiles
#define TTOT (NQT * NKT)          // 8192 global tile-pairs
#define NCTA 148
#define NT   256

#define LOG2E 1.4426950408889634f

// ---------------- global scratch (static; no allocation) ----------------
__device__ __align__(256) __half g_Qh[SQc * DHc];
__device__ __align__(256) __half g_Ql[SQc * DHc];
__device__ __align__(256) __half g_Kh[SKc * DHc];
__device__ __align__(256) __half g_Kl[SKc * DHc];
__device__ __align__(256) __half g_Vt[DHc * SKc];     // V transposed: [d][key]
// per-CTA partials: each CTA covers <= 2 q-tiles (range <= 56 < 128)
__device__ __align__(256) float g_pO[NCTA][2][BMc * DHc];
__device__ __align__(256) float g_pl[NCTA][2][BMc];
__device__ __align__(256) float g_pm[NCTA][2][BMc];

__device__ __forceinline__ int cta_start(int c) {
    return (int)(((long long)c * TTOT) / NCTA);
}

// ---------------- helpers ----------------
__device__ __forceinline__ uint32_t sw128(uint32_t o) { return o ^ ((o >> 3) & 0x70); }

__device__ __forceinline__ uint32_t smem_u32(const void* p) {
    uint32_t a;
    asm("{ .reg .u64 t; cvta.to.shared.u64 t, %1; cvt.u32.u64 %0, t; }" : "=r"(a) : "l"(p));
    return a;
}

__device__ __forceinline__ void cp16(uint32_t dst, const void* src) {
    asm volatile("cp.async.cg.shared.global [%0], [%1], 16;" :: "r"(dst), "l"(src));
}
__device__ __forceinline__ void cp_commit() { asm volatile("cp.async.commit_group;" ::: "memory"); }

__device__ __forceinline__ void ldsm4(uint32_t* r, uint32_t addr) {
    asm volatile("ldmatrix.sync.aligned.m8n8.x4.shared.b16 {%0,%1,%2,%3}, [%4];"
        : "=r"(r[0]), "=r"(r[1]), "=r"(r[2]), "=r"(r[3]) : "r"(addr));
}

__device__ __forceinline__ void mma16816(float* d, const uint32_t* a, uint32_t b0, uint32_t b1) {
    asm volatile(
        "mma.sync.aligned.m16n8k16.row.col.f32.f16.f16.f32 "
        "{%0,%1,%2,%3}, {%4,%5,%6,%7}, {%8,%9}, {%0,%1,%2,%3};"
        : "+f"(d[0]), "+f"(d[1]), "+f"(d[2]), "+f"(d[3])
        : "r"(a[0]), "r"(a[1]), "r"(a[2]), "r"(a[3]), "r"(b0), "r"(b1));
}

__device__ __forceinline__ float ex2f(float x) {
    float r;
    asm("ex2.approx.f32 %0, %1;" : "=f"(r) : "f"(x));
    return r;
}

__device__ __forceinline__ uint32_t packh2(float lo, float hi) {
    uint32_t u;
    asm("cvt.rn.f16x2.f32 %0, %1, %2;" : "=r"(u) : "f"(hi), "f"(lo));
    return u;
}

__device__ __forceinline__ uint32_t ex2h2(float z0, float z1) {
    uint32_t zp, pp;
    asm("cvt.rn.f16x2.f32 %0, %1, %2;" : "=r"(zp) : "f"(z1), "f"(z0));
    asm("ex2.approx.f16x2 %0, %1;" : "=r"(pp) : "r"(zp));
    return pp;
}

// ---------------- preprocessing ----------------
__global__ void convert_qk(const float4* __restrict__ Q, const float4* __restrict__ K) {
    int i = blockIdx.x * 256 + threadIdx.x;
    float4 q = Q[i];
    uint32_t h01 = packh2(q.x, q.y);
    uint32_t h23 = packh2(q.z, q.w);
    float2 f01 = __half22float2(*(__half2*)&h01);
    float2 f23 = __half22float2(*(__half2*)&h23);
    ((uint2*)g_Qh)[i] = make_uint2(h01, h23);
    ((uint2*)g_Ql)[i] = make_uint2(packh2(q.x - f01.x, q.y - f01.y),
                                   packh2(q.z - f23.x, q.w - f23.y));
    float4 k = K[i];
    h01 = packh2(k.x, k.y);
    h23 = packh2(k.z, k.w);
    f01 = __half22float2(*(__half2*)&h01);
    f23 = __half22float2(*(__half2*)&h23);
    ((uint2*)g_Kh)[i] = make_uint2(h01, h23);
    ((uint2*)g_Kl)[i] = make_uint2(packh2(k.x - f01.x, k.y - f01.y),
                                   packh2(k.z - f23.x, k.w - f23.y));
}

__global__ void convert_vt(const float* __restrict__ V) {
    __shared__ float t[32][33];
    int s0 = blockIdx.x * 32, d0 = blockIdx.y * 32;
    int tx = threadIdx.x, ty = threadIdx.y;   // 32 x 8
    #pragma unroll
    for (int i = 0; i < 4; i++)
        t[ty * 4 + i][tx] = V[(size_t)(s0 + ty * 4 + i) * DHc + d0 + tx];
    __syncthreads();
    int tid = ty * 32 + tx;
    int dl = tid >> 3;
    int sl = (tid & 7) * 4;
    __half2 h0 = __floats2half2_rn(t[sl][dl],     t[sl + 1][dl]);
    __half2 h1 = __floats2half2_rn(t[sl + 2][dl], t[sl + 3][dl]);
    uint2 u; u.x = *(uint32_t*)&h0; u.y = *(uint32_t*)&h1;
    *(uint2*)&g_Vt[(size_t)(d0 + dl) * SKc + s0 + sl] = u;
}

// merge <=4 per-CTA partials per q-row — branch-free scalar unrolled version
__global__ void combine_out(float4* __restrict__ O) {
    int idx = blockIdx.x * 256 + threadIdx.x;   // SQ * 32 float4
    int row = idx >> 5;
    int c4  = idx & 31;
    int qt  = row >> 7, qr = row & 127;
    int t0  = qt << 7, t1 = t0 + BMc;

    // closed-form first covering CTA (guess never overshoots; gap ~55 => <=1 step,
    // second check for safety)
    int c0 = (int)(((long long)t0 * NCTA) / TTOT);
    if (cta_start(c0 + 1) <= t0) c0++;
    if (cta_start(c0 + 1) <= t0) c0++;

    // partial i = CTA c0+i; valid while its range intersects [t0, t1)
    int  c1 = c0 + 1, c2 = c0 + 2, c3 = c0 + 3;
    int  s0i = qt - (cta_start(c0) >> 7);
    bool v1 = (c1 < NCTA) && (cta_start(c1) < t1);
    bool v2 = (c2 < NCTA) && (cta_start(c2) < t1);
    bool v3 = (c3 < NCTA) && (cta_start(c3) < t1);
    int  s1i = v1 ? (qt - (cta_start(c1) >> 7)) : 0;
    int  s2i = v2 ? (qt - (cta_start(c2) >> 7)) : 0;
    int  s3i = v3 ? (qt - (cta_start(c3) >> 7)) : 0;
    if (!v1) c1 = c0;
    if (!v2) c2 = c0;
    if (!v3) c3 = c0;

    float m0 = g_pm[c0][s0i][qr];
    float m1 = v1 ? g_pm[c1][s1i][qr] : -INFINITY;
    float m2 = v2 ? g_pm[c2][s2i][qr] : -INFINITY;
    float m3 = v3 ? g_pm[c3][s3i][qr] : -INFINITY;
    float M  = fmaxf(fmaxf(m0, m1), fmaxf(m2, m3));

    float w0 = ex2f((m0 - M) * LOG2E);
    float w1 = v1 ? ex2f((m1 - M) * LOG2E) : 0.0f;
    float w2 = v2 ? ex2f((m2 - M) * LOG2E) : 0.0f;
    float w3 = v3 ? ex2f((m3 - M) * LOG2E) : 0.0f;

    float L = g_pl[c0][s0i][qr] * w0;
    if (v1) L += g_pl[c1][s1i][qr] * w1;
    if (v2) L += g_pl[c2][s2i][qr] * w2;
    if (v3) L += g_pl[c3][s3i][qr] * w3;
    float inv = 1.0f / L;
    w0 *= inv; w1 *= inv; w2 *= inv; w3 *= inv;

    int off = qr * DHc + c4 * 4;
    float4 a0 = *(const float4*)&g_pO[c0][s0i][off];
    float4 r;
    r.x = a0.x * w0; r.y = a0.y * w0; r.z = a0.z * w0; r.w = a0.w * w0;
    if (v1) {
        float4 a = *(const float4*)&g_pO[c1][s1i][off];
        r.x += a.x * w1; r.y += a.y * w1; r.z += a.z * w1; r.w += a.w * w1;
    }
    if (v2) {
        float4 a = *(const float4*)&g_pO[c2][s2i][off];
        r.x += a.x * w2; r.y += a.y * w2; r.z += a.z * w2; r.w += a.w * w2;
    }
    if (v3) {
        float4 a = *(const float4*)&g_pO[c3][s3i][off];
        r.x += a.x * w3; r.y += a.y * w3; r.z += a.z * w3; r.w += a.w * w3;
    }
    O[(size_t)row * 32 + c4] = r;
}

// ---------------- main kernel (identical to R13 winner) ----------------
// stage (48KB): Kh c0 @0, Kh c1 @8192, Kl c0 @16384, Kl c1 @24576, Vt @32768 (16K)
#define STG        49152
#define QLB_OFF    (3 * STG)
#define SMEM_TOTAL (3 * STG + 32768)

__device__ __forceinline__ void load_tile(uint32_t SB, int kb, int tid) {
    #pragma unroll
    for (int it = 0; it < 12; it++) {
        int u = it * NT + tid;
        if (u < 2048) {
            int sp = u >> 10;
            int i  = u & 1023;
            int ch = i >> 9;
            int r  = (i >> 3) & 63;
            int cb = i & 7;
            uint32_t dst = SB + (uint32_t)sp * 16384u + (uint32_t)ch * 8192u
                         + sw128((uint32_t)(r * 128 + cb * 16));
            const __half* src = (sp ? g_Kl : g_Kh) + ((size_t)(kb + r) * DHc + ch * 64 + cb * 8);
            cp16(dst, src);
        } else {
            int v  = u - 2048;
            int r  = v >> 3;
            int cb = v & 7;
            uint32_t dst = SB + 32768u + sw128((uint32_t)(r * 128 + cb * 16));
            const __half* src = g_Vt + ((size_t)r * SKc + kb + cb * 8);
            cp16(dst, src);
        }
    }
}

__global__ void __launch_bounds__(NT, 1) attn_hmma() {
    extern __shared__ char smem[];
    const uint32_t sb  = smem_u32(smem);
    const uint32_t QLB = sb + QLB_OFF;
    const int tid   = threadIdx.x;
    const int w     = tid >> 5;
    const int lane  = tid & 31;
    const int wbase = w * 16;
    const int cidx  = blockIdx.x;
    const int gs    = cta_start(cidx);
    const int ge    = cta_start(cidx + 1);

    const int krow_b = (lane & 7) * 128 + ((lane >> 3) & 3) * 16;
    const int arow   = wbase + ((lane >> 3) & 1) * 8 + (lane & 7);
    const int adb    = (lane >> 4) * 16;
    const int vrow_b = (((lane >> 4) & 1) * 8 + (lane & 7)) * 128 + ((lane >> 3) & 1) * 16;
    const uint32_t ONESH2 = 0x3C003C00u;

    // prologue prefetch of first two K/V tiles
    load_tile(sb + (uint32_t)(gs % 3) * STG, (gs & (NKT - 1)) << 6, tid); cp_commit();
    load_tile(sb + (uint32_t)((gs + 1) % 3) * STG, ((gs + 1) & (NKT - 1)) << 6, tid); cp_commit();

    uint32_t qh[8][4];
    float o[16][4];
    float lacc[4];
    float m0 = -INFINITY, m1 = -INFINITY;
    int cur_qt = -1, slot = -1;

    for (int g = gs; g < ge; g++) {
        const int qt = g >> 7;   // NKT = 128

        if (qt != cur_qt) {
            // ---- flush previous q-tile partial ----
            if (slot >= 0) {
                int r0 = wbase + (lane >> 2), r1 = r0 + 8;
                int c2 = (lane & 3) * 2;
                float* op = g_pO[cidx][slot];
                #pragma unroll
                for (int n = 0; n < 16; n++) {
                    *(float2*)&op[r0 * DHc + n * 8 + c2] = make_float2(o[n][0], o[n][1]);
                    *(float2*)&op[r1 * DHc + n * 8 + c2] = make_float2(o[n][2], o[n][3]);
                }
                if ((lane & 3) == 0) {
                    g_pl[cidx][slot][r0] = lacc[0];  g_pl[cidx][slot][r1] = lacc[2];
                    g_pm[cidx][slot][r0] = m0;       g_pm[cidx][slot][r1] = m1;
                }
            }
            slot++;
            #pragma unroll
            for (int n = 0; n < 16; n++)
                #pragma unroll
                for (int j = 0; j < 4; j++) o[n][j] = 0.0f;
            lacc[0] = lacc[1] = lacc[2] = lacc[3] = 0.0f;
            m0 = -INFINITY; m1 = -INFINITY;

            // ---- load Q(qt): Qh -> free stage (g+2)%3, Ql -> QLB ----
            __syncthreads();   // all warps done with prior compute/stage reads
            const uint32_t QSTG = sb + (uint32_t)((g + 2) % 3) * STG;
            const int qrow0 = qt * BMc;
            #pragma unroll
            for (int it = 0; it < 16; it++) {
                int u  = it * NT + tid;         // 0..4095
                int sp = u >> 11;               // 0: Qh, 1: Ql
                int i  = u & 2047;
                int ch = i >> 10;
                int r  = (i >> 3) & 127;
                int cb = i & 7;
                uint32_t base = sp ? QLB : QSTG;
                uint32_t dst  = base + (uint32_t)ch * 16384u
                              + sw128((uint32_t)(r * 128 + cb * 16));
                const __half* src = (sp ? g_Ql : g_Qh)
                                  + ((size_t)(qrow0 + r) * DHc + ch * 64 + cb * 8);
                cp16(dst, src);
            }
            cp_commit();
            asm volatile("cp.async.wait_group 0;" ::: "memory");
            __syncthreads();
            #pragma unroll
            for (int ks = 0; ks < 8; ks++) {
                int ch = ks >> 2;
                ldsm4(qh[ks], QSTG + (uint32_t)ch * 16384u
                              + sw128((uint32_t)(arow * 128 + (ks & 3) * 32 + adb)));
            }
            cur_qt = qt;
        }

        const uint32_t SB = sb + (uint32_t)(g % 3) * STG;

        if (g == ge - 1) asm volatile("cp.async.wait_group 0;" ::: "memory");
        else             asm volatile("cp.async.wait_group 1;" ::: "memory");
        __syncthreads();

        if (g + 2 < ge) {
            load_tile(sb + (uint32_t)((g + 2) % 3) * STG, ((g + 2) & (NKT - 1)) << 6, tid);
            cp_commit();
        }

        // ---- S = (Qh+Ql)(Kh+Kl)^T, all f32 accum ----
        float s[8][4];
        #pragma unroll
        for (int n = 0; n < 8; n++)
            #pragma unroll
            for (int j = 0; j < 4; j++) s[n][j] = 0.0f;

        #pragma unroll
        for (int ch = 0; ch < 2; ch++) {
            #pragma unroll
            for (int ks2 = 0; ks2 < 2; ks2++) {
                const int ksA = ch * 4 + ks2 * 2;
                uint32_t bh[8][4];
                #pragma unroll
                for (int n = 0; n < 8; n++)
                    ldsm4(bh[n], SB + (uint32_t)ch * 8192u
                                 + sw128((uint32_t)(n * 1024 + ks2 * 64 + krow_b)));
                uint32_t qlf[2][4];
                #pragma unroll
                for (int kd = 0; kd < 2; kd++) {
                    int ks  = ksA + kd;
                    int dby = (ks & 3) * 32 + adb;
                    ldsm4(qlf[kd], QLB + (uint32_t)ch * 16384u
                                   + sw128((uint32_t)(arow * 128 + dby)));
                }
                #pragma unroll
                for (int n = 0; n < 8; n++) {
                    mma16816(s[n], qh[ksA],     bh[n][0], bh[n][1]);
                    mma16816(s[n], qh[ksA + 1], bh[n][2], bh[n][3]);
                    mma16816(s[n], qlf[0],      bh[n][0], bh[n][1]);
                    mma16816(s[n], qlf[1],      bh[n][2], bh[n][3]);
                }
                uint32_t bl[8][4];
                #pragma unroll
                for (int n = 0; n < 8; n++)
                    ldsm4(bl[n], SB + 16384u + (uint32_t)ch * 8192u
                                 + sw128((uint32_t)(n * 1024 + ks2 * 64 + krow_b)));
                #pragma unroll
                for (int n = 0; n < 8; n++) {
                    mma16816(s[n], qh[ksA],     bl[n][0], bl[n][1]);
                    mma16816(s[n], qh[ksA + 1], bl[n][2], bl[n][3]);
                }
            }
        }

        // ---- online softmax ----
        float t0 = s[0][0], t1 = s[0][2];
        #pragma unroll
        for (int n = 0; n < 8; n++) {
            t0 = fmaxf(t0, fmaxf(s[n][0], s[n][1]));
            t1 = fmaxf(t1, fmaxf(s[n][2], s[n][3]));
        }
        t0 = fmaxf(t0, __shfl_xor_sync(0xffffffffu, t0, 1));
        t0 = fmaxf(t0, __shfl_xor_sync(0xffffffffu, t0, 2));
        t1 = fmaxf(t1, __shfl_xor_sync(0xffffffffu, t1, 1));
        t1 = fmaxf(t1, __shfl_xor_sync(0xffffffffu, t1, 2));

        float mn0 = fmaxf(m0, t0), mn1 = fmaxf(m1, t1);
        float a0 = ex2f((m0 - mn0) * LOG2E), a1 = ex2f((m1 - mn1) * LOG2E);
        m0 = mn0; m1 = mn1;

        if (!__all_sync(0xffffffffu, (a0 == 1.0f) & (a1 == 1.0f))) {
            #pragma unroll
            for (int n = 0; n < 16; n++) {
                o[n][0] *= a0; o[n][1] *= a0;
                o[n][2] *= a1; o[n][3] *= a1;
            }
            lacc[0] *= a0; lacc[1] *= a0;
            lacc[2] *= a1; lacc[3] *= a1;
        }

        const float nm0 = -mn0 * LOG2E, nm1 = -mn1 * LOG2E;
        uint32_t ph[8][2];
        #pragma unroll
        for (int n = 0; n < 8; n++) {
            ph[n][0] = ex2h2(fmaf(s[n][0], LOG2E, nm0), fmaf(s[n][1], LOG2E, nm0));
            ph[n][1] = ex2h2(fmaf(s[n][2], LOG2E, nm1), fmaf(s[n][3], LOG2E, nm1));
        }

        // ---- O += P V ; l += P * ones ----
        #pragma unroll
        for (int ks = 0; ks < 4; ks++) {
            uint32_t A[4] = { ph[2 * ks][0], ph[2 * ks][1],
                              ph[2 * ks + 1][0], ph[2 * ks + 1][1] };
            mma16816(lacc, A, ONESH2, ONESH2);
            uint32_t bv[8][4];
            #pragma unroll
            for (int dp = 0; dp < 8; dp++)
                ldsm4(bv[dp], SB + 32768u
                              + sw128((uint32_t)(dp * 2048 + ks * 32 + vrow_b)));
            #pragma unroll
            for (int dp = 0; dp < 8; dp++) {
                mma16816(o[2 * dp],     A, bv[dp][0], bv[dp][1]);
                mma16816(o[2 * dp + 1], A, bv[dp][2], bv[dp][3]);
            }
        }
    }

    // ---- final flush ----
    {
        int r0 = wbase + (lane >> 2), r1 = r0 + 8;
        int c2 = (lane & 3) * 2;
        float* op = g_pO[cidx][slot];
        #pragma unroll
        for (int n = 0; n < 16; n++) {
            *(float2*)&op[r0 * DHc + n * 8 + c2] = make_float2(o[n][0], o[n][1]);
            *(float2*)&op[r1 * DHc + n * 8 + c2] = make_float2(o[n][2], o[n][3]);
        }
        if ((lane & 3) == 0) {
            g_pl[cidx][slot][r0] = lacc[0];  g_pl[cidx][slot][r1] = lacc[2];
            g_pm[cidx][slot][r0] = m0;       g_pm[cidx][slot][r1] = m1;
        }
    }
}

// ---------------- launcher ----------------
extern "C" void kernel_launch(void* const* d_in, const int* in_sizes, int n_in,
                              void* d_out, int out_size)
{
    const float* Q = (const float*)d_in[0];
    const float* K = (const float*)d_in[1];
    const float* V = (const float*)d_in[2];
    float* O = (float*)d_out;

    cudaFuncSetAttribute(attn_hmma, cudaFuncAttributeMaxDynamicSharedMemorySize, SMEM_TOTAL);

    convert_qk<<<SQc * DHc / 4 / 256, 256>>>((const float4*)Q, (const float4*)K);
    convert_vt<<<dim3(SKc / 32, DHc / 32), dim3(32, 8)>>>(V);
    attn_hmma<<<NCTA, NT, SMEM_TOTAL>>>();
    combine_out<<<SQc * 32 / 256, 256>>>((float4*)O);
}